// round 9
// baseline (speedup 1.0000x reference)
#include <cuda_runtime.h>
#include <cuda_fp16.h>
#include <mma.h>
#include <cstdint>

namespace wm = nvcuda::wmma;

// ---------------------------------------------------------------------------
// Scratch (device globals)
// ---------------------------------------------------------------------------
__device__ __half g_q [2u * 2048u * 1024u];
__device__ __half g_k [2u * 2048u * 1024u];
__device__ __half g_v [2u * 2048u * 1024u];
__device__ __half g_yt[2u * 2048u * 1024u];
__device__ __half g_xh   [4096u * 1024u];
__device__ __half g_wqkvh[1024u * 3072u];
__device__ __half g_wprojh[1024u * 1024u];

// ---------------------------------------------------------------------------
// cp.async helpers
// ---------------------------------------------------------------------------
__device__ __forceinline__ uint32_t smem_u32(const void* p) {
    return (uint32_t)__cvta_generic_to_shared(p);
}
__device__ __forceinline__ void cp16(uint32_t dst, const void* src) {
    asm volatile("cp.async.cg.shared.global [%0], [%1], 16;"
                 :: "r"(dst), "l"(src) : "memory");
}
__device__ __forceinline__ void cp_commit() {
    asm volatile("cp.async.commit_group;" ::: "memory");
}
template <int N>
__device__ __forceinline__ void cp_wait() {
    asm volatile("cp.async.wait_group %0;" :: "n"(N) : "memory");
}

// ---------------------------------------------------------------------------
// fp32 -> fp16 conversion pass (8 elements/thread)
// ---------------------------------------------------------------------------
__global__ void to_half_kernel(const float* __restrict__ in,
                               __half* __restrict__ out, int n8)
{
    int i = blockIdx.x * blockDim.x + threadIdx.x;
    if (i < n8) {
        float4 a = ((const float4*)in)[i * 2];
        float4 b = ((const float4*)in)[i * 2 + 1];
        __half h[8];
        h[0] = __float2half_rn(a.x); h[1] = __float2half_rn(a.y);
        h[2] = __float2half_rn(a.z); h[3] = __float2half_rn(a.w);
        h[4] = __float2half_rn(b.x); h[5] = __float2half_rn(b.y);
        h[6] = __float2half_rn(b.z); h[7] = __float2half_rn(b.w);
        ((uint4*)out)[i] = *(uint4*)h;
    }
}

// ---------------------------------------------------------------------------
// FP16 WMMA GEMM (fp32 accumulate), 3-stage cp.async, 2 CTAs/SM.
// C = A[M,K] @ B[K,N] + bias[N]. BM=BN=128, BK=32, 256 thr (8 warps 4x2).
// ---------------------------------------------------------------------------
#define G_ALD 40
#define G_BLD 136
#define G_ASZ (128 * G_ALD)
#define G_BSZ (32 * G_BLD)
#define G_STG 3
#define G_SMEM_BYTES (G_STG * (G_ASZ + G_BSZ) * 2 + 16 * G_BLD * 4)  // 65536

template <int ROUND_OUT>
__global__ __launch_bounds__(256, 2) void gemm_fp16_kernel(
    const __half* __restrict__ A, const __half* __restrict__ B,
    const float* __restrict__ bias,
    void* __restrict__ out0v, void* __restrict__ out1v, void* __restrict__ out2v,
    int M, int N, int K)
{
    extern __shared__ char gsmc[];
    __half* gsm  = (__half*)gsmc;
    float*  Brep = (float*)(gsmc + G_STG * (G_ASZ + G_BSZ) * 2);

    const int tid  = threadIdx.x;
    const int wid  = tid >> 5;
    const int wmi  = wid & 3;
    const int wni  = wid >> 2;
    const int m0   = blockIdx.y * 128;
    const int n0   = blockIdx.x * 128;

    for (int i = tid; i < 16 * 128; i += 256) {
        int r = i >> 7, c = i & 127;
        Brep[r * G_BLD + c] = bias[n0 + c];
    }
    __syncthreads();

    wm::fragment<wm::accumulator, 16, 16, 16, float> acc[2][4];
#pragma unroll
    for (int mi = 0; mi < 2; ++mi)
#pragma unroll
        for (int ni = 0; ni < 4; ++ni)
            wm::load_matrix_sync(acc[mi][ni], Brep + wni * 64 + ni * 16, G_BLD,
                                 wm::mem_row_major);
    __syncthreads();

    const int iters = K >> 5;

    auto issue_stage = [&](int stage) {
        const int s = stage % G_STG;
        const int k0 = stage << 5;
        __half* as = gsm + s * G_ASZ;
        __half* bs = gsm + G_STG * G_ASZ + s * G_BSZ;
#pragma unroll
        for (int t = 0; t < 2; ++t) {
            int f = tid + t * 256;
            int r = f >> 2, c8 = (f & 3) << 3;
            cp16(smem_u32(as + r * G_ALD + c8),
                 A + (size_t)(m0 + r) * K + k0 + c8);
        }
#pragma unroll
        for (int t = 0; t < 2; ++t) {
            int f = tid + t * 256;
            int r = f >> 4, c8 = (f & 15) << 3;
            cp16(smem_u32(bs + r * G_BLD + c8),
                 B + (size_t)(k0 + r) * N + n0 + c8);
        }
        cp_commit();
    };

    issue_stage(0);
    issue_stage(1);

    for (int it = 0; it < iters; ++it) {
        cp_wait<1>();
        __syncthreads();

        if (it + 2 < iters) issue_stage(it + 2);
        else                cp_commit();

        const int s = it % G_STG;
        const __half* as = gsm + s * G_ASZ;
        const __half* bs = gsm + G_STG * G_ASZ + s * G_BSZ;
#pragma unroll
        for (int ks = 0; ks < 2; ++ks) {
            wm::fragment<wm::matrix_a, 16, 16, 16, __half, wm::row_major> af[2];
            wm::fragment<wm::matrix_b, 16, 16, 16, __half, wm::row_major> bf[4];
#pragma unroll
            for (int mi = 0; mi < 2; ++mi)
                wm::load_matrix_sync(af[mi], as + (wmi * 32 + mi * 16) * G_ALD + ks * 16, G_ALD);
#pragma unroll
            for (int ni = 0; ni < 4; ++ni)
                wm::load_matrix_sync(bf[ni], bs + (ks * 16) * G_BLD + wni * 64 + ni * 16, G_BLD);
#pragma unroll
            for (int mi = 0; mi < 2; ++mi)
#pragma unroll
                for (int ni = 0; ni < 4; ++ni)
                    wm::mma_sync(acc[mi][ni], af[mi], bf[ni], acc[mi][ni]);
        }
        __syncthreads();
    }

    const int nc = n0 & 1023;
    if (ROUND_OUT) {
        __half* outp = (n0 < 1024) ? (__half*)out0v
                     : ((n0 < 2048) ? (__half*)out1v : (__half*)out2v);
        float* stg = (float*)gsmc;
#pragma unroll
        for (int mi = 0; mi < 2; ++mi) {
            __syncthreads();
#pragma unroll
            for (int ni = 0; ni < 4; ++ni)
                wm::store_matrix_sync(stg + (wmi * 16) * G_BLD + wni * 64 + ni * 16,
                                      acc[mi][ni], G_BLD, wm::mem_row_major);
            __syncthreads();
#pragma unroll
            for (int t = 0; t < 4; ++t) {
                int idx = tid + t * 256;
                int sr = idx >> 4;
                int c8 = (idx & 15) << 3;
                int grow = m0 + (sr >> 4) * 32 + mi * 16 + (sr & 15);
                const float* s = stg + sr * G_BLD + c8;
                __half h[8];
#pragma unroll
                for (int j = 0; j < 8; ++j) h[j] = __float2half_rn(s[j]);
                *(uint4*)(outp + (size_t)grow * 1024 + nc + c8) = *(uint4*)h;
            }
        }
    } else {
        float* outp = (n0 < 1024) ? (float*)out0v
                    : ((n0 < 2048) ? (float*)out1v : (float*)out2v);
#pragma unroll
        for (int mi = 0; mi < 2; ++mi)
#pragma unroll
            for (int ni = 0; ni < 4; ++ni) {
                float* p = outp + (size_t)(m0 + wmi * 32 + mi * 16) * 1024
                                + nc + wni * 64 + ni * 16;
                wm::store_matrix_sync(p, acc[mi][ni], 1024, wm::mem_row_major);
            }
    }
}

// ---------------------------------------------------------------------------
// Flash attention (causal), FP16 WMMA. Br=128, Bc=128, hd=64, 512 threads.
// K/V double-buffered via cp.async. S fp32 in smem; P (half) ALIASED onto the
// S buffer (each thread writes P into bytes of S floats its own warp already
// consumed; warp-uniform read -> shfl.sync -> write ordering makes this safe).
// ---------------------------------------------------------------------------
#define FS_LD  72      // half lda for Q/K/V and fp32 lda for Oacc
#define FS_SLD 136     // fp32 lda for S (128 cols + 8 pad)
#define FS_PLD 272     // half lda for P (aliased on S buffer)
// smem byte offsets
#define FS_QS   0
#define FS_SS   18432
#define FS_OA   88064
#define FS_K0   124928
#define FS_K1   143360
#define FS_V0   161792
#define FS_V1   180224
#define FS_SMEM 198656

__global__ __launch_bounds__(512) void flash_fp16_kernel(
    const __half* __restrict__ Qg, const __half* __restrict__ Kg,
    const __half* __restrict__ Vg, __half* __restrict__ yt)
{
    extern __shared__ char smc[];
    __half* Qs  = (__half*)(smc + FS_QS);
    float*  Ss  = (float*)(smc + FS_SS);
    __half* Ps  = (__half*)(smc + FS_SS);     // aliased
    float*  Oacc= (float*)(smc + FS_OA);
    __half* KsA[2] = { (__half*)(smc + FS_K0), (__half*)(smc + FS_K1) };
    __half* VsA[2] = { (__half*)(smc + FS_V0), (__half*)(smc + FS_V1) };

    const int qt  = gridDim.x - 1 - blockIdx.x;   // longest-first
    const int bh  = blockIdx.y;
    const int tid = threadIdx.x;
    const int wid = tid >> 5;
    const int wmi = wid & 3;       // 32-row stripe (of 128)
    const int wni = wid >> 2;      // S: 32-col stripe (of 128); PV: 16-col (of 64)

    const int r   = tid >> 2;      // softmax row (0..127)
    const int qq  = tid & 3;       // S: 32-col quarter; O: 16-col quarter

    const size_t head_off = (size_t)bh * 131072u;
    const __half* qb = Qg + head_off + (size_t)qt * 8192u;

    auto issue_kv = [&](int kt, int buf) {
        const __half* kb = Kg + head_off + (size_t)kt * 8192u;
        const __half* vb = Vg + head_off + (size_t)kt * 8192u;
        // 128 rows x 64 halves: 8 chunks/row -> 1024 chunks each for K and V
#pragma unroll
        for (int t = 0; t < 2; ++t) {
            int f = tid + t * 512;
            int rr = f >> 3, c8 = (f & 7) << 3;
            cp16(smem_u32(KsA[buf] + rr * FS_LD + c8), kb + rr * 64 + c8);
            cp16(smem_u32(VsA[buf] + rr * FS_LD + c8), vb + rr * 64 + c8);
        }
        cp_commit();
    };

    issue_kv(0, 0);

    // Load Q (scaled by 0.125 — exact in fp16) + zero Oacc
    const __half2 sc = __half2half2(__float2half_rn(0.125f));
#pragma unroll
    for (int t = 0; t < 2; ++t) {
        int f = tid + t * 512;
        int rr = f >> 3, c8 = (f & 7) << 3;
        uint4 raw = *(const uint4*)(qb + rr * 64 + c8);
        __half2* hp = (__half2*)&raw;
#pragma unroll
        for (int j = 0; j < 4; ++j) hp[j] = __hmul2(hp[j], sc);
        *(uint4*)(Qs + rr * FS_LD + c8) = raw;
    }
    for (int f = tid; f < 128 * FS_LD / 4; f += 512) {
        float4 z = {0.f, 0.f, 0.f, 0.f};
        *(float4*)(Oacc + f * 4) = z;
    }

    float mrow = -1e30f, lrow = 0.0f;
    int buf = 0;
    const int n_kt = qt + 1;

    for (int kt = 0; kt < n_kt; ++kt) {
        cp_wait<0>();
        __syncthreads();

        if (kt + 1 < n_kt) issue_kv(kt + 1, buf ^ 1);

        // ---- S = Q @ K^T : warp tile 32x32, 4 k-steps ----
        {
            wm::fragment<wm::accumulator, 16, 16, 16, float> sacc[2][2];
#pragma unroll
            for (int mi = 0; mi < 2; ++mi)
#pragma unroll
                for (int ni = 0; ni < 2; ++ni) wm::fill_fragment(sacc[mi][ni], 0.0f);
#pragma unroll
            for (int ks = 0; ks < 4; ++ks) {
                wm::fragment<wm::matrix_a, 16, 16, 16, __half, wm::row_major> af[2];
                wm::fragment<wm::matrix_b, 16, 16, 16, __half, wm::col_major> bf[2];
#pragma unroll
                for (int mi = 0; mi < 2; ++mi)
                    wm::load_matrix_sync(af[mi], Qs + (wmi * 32 + mi * 16) * FS_LD + ks * 16, FS_LD);
#pragma unroll
                for (int ni = 0; ni < 2; ++ni)
                    wm::load_matrix_sync(bf[ni], KsA[buf] + (wni * 32 + ni * 16) * FS_LD + ks * 16, FS_LD);
#pragma unroll
                for (int mi = 0; mi < 2; ++mi)
#pragma unroll
                    for (int ni = 0; ni < 2; ++ni)
                        wm::mma_sync(sacc[mi][ni], af[mi], bf[ni], sacc[mi][ni]);
            }
#pragma unroll
            for (int mi = 0; mi < 2; ++mi)
#pragma unroll
                for (int ni = 0; ni < 2; ++ni)
                    wm::store_matrix_sync(Ss + (wmi * 32 + mi * 16) * FS_SLD + wni * 32 + ni * 16,
                                          sacc[mi][ni], FS_SLD, wm::mem_row_major);
        }
        __syncthreads();

        // ---- Online softmax (row r, cols qq*32..qq*32+31) + O rescale ----
        {
            float s[32];
            const float* srow = Ss + r * FS_SLD + qq * 32;
#pragma unroll
            for (int j = 0; j < 32; ++j) s[j] = srow[j];
            if (kt == qt) {     // diagonal tile: causal mask
#pragma unroll
                for (int j = 0; j < 32; ++j)
                    if (qq * 32 + j > r) s[j] = -1e30f;
            }
            float mx = -1e30f;
#pragma unroll
            for (int j = 0; j < 32; ++j) mx = fmaxf(mx, s[j]);
            mx = fmaxf(mx, __shfl_xor_sync(0xffffffffu, mx, 1));
            mx = fmaxf(mx, __shfl_xor_sync(0xffffffffu, mx, 2));
            // shfl.sync above also orders: all 4 row-lanes finished reading S

            float mn = fmaxf(mrow, mx);
            float alpha = __expf(mrow - mn);
            mrow = mn;

            float sum = 0.0f;
            __half ph[32];
#pragma unroll
            for (int j = 0; j < 32; ++j) {
                float p = __expf(s[j] - mn);
                sum += p;
                ph[j] = __float2half_rn(p);
            }
            __syncwarp();   // ensure every lane in warp is past its S reads
            __half* prow = Ps + r * FS_PLD + qq * 32;
            *(uint4*)(prow)      = *(uint4*)(ph);
            *(uint4*)(prow + 8)  = *(uint4*)(ph + 8);
            *(uint4*)(prow + 16) = *(uint4*)(ph + 16);
            *(uint4*)(prow + 24) = *(uint4*)(ph + 24);

            sum += __shfl_xor_sync(0xffffffffu, sum, 1);
            sum += __shfl_xor_sync(0xffffffffu, sum, 2);
            lrow = lrow * alpha + sum;

            // rescale running O row (16 cols per thread)
            float* oa = Oacc + r * FS_LD + qq * 16;
#pragma unroll
            for (int j4 = 0; j4 < 4; ++j4) {
                float4 a = *(float4*)(oa + j4 * 4);
                a.x *= alpha; a.y *= alpha; a.z *= alpha; a.w *= alpha;
                *(float4*)(oa + j4 * 4) = a;
            }
        }
        __syncthreads();

        // ---- Oacc += P @ V : warp tile 32x16, 8 k-steps ----
        {
            wm::fragment<wm::accumulator, 16, 16, 16, float> oacc[2];
#pragma unroll
            for (int mi = 0; mi < 2; ++mi)
                wm::load_matrix_sync(oacc[mi],
                    Oacc + (wmi * 32 + mi * 16) * FS_LD + wni * 16, FS_LD, wm::mem_row_major);
#pragma unroll
            for (int ks = 0; ks < 8; ++ks) {
                wm::fragment<wm::matrix_a, 16, 16, 16, __half, wm::row_major> af[2];
                wm::fragment<wm::matrix_b, 16, 16, 16, __half, wm::row_major> bf;
#pragma unroll
                for (int mi = 0; mi < 2; ++mi)
                    wm::load_matrix_sync(af[mi], Ps + (wmi * 32 + mi * 16) * FS_PLD + ks * 16, FS_PLD);
                wm::load_matrix_sync(bf, VsA[buf] + (ks * 16) * FS_LD + wni * 16, FS_LD);
#pragma unroll
                for (int mi = 0; mi < 2; ++mi)
                    wm::mma_sync(oacc[mi], af[mi], bf, oacc[mi]);
            }
#pragma unroll
            for (int mi = 0; mi < 2; ++mi)
                wm::store_matrix_sync(Oacc + (wmi * 32 + mi * 16) * FS_LD + wni * 16,
                                      oacc[mi], FS_LD, wm::mem_row_major);
        }
        __syncthreads();
        buf ^= 1;
    }

    // ---- Epilogue: normalize, write half to [B,T,H,hd] ----
    {
        const int b = bh >> 4;
        const int h = bh & 15;
        const float inv = 1.0f / lrow;
        const int tq = qt * 128 + r;
        const float* oa = Oacc + r * FS_LD + qq * 16;
        __half* dst = yt + ((size_t)(b * 2048 + tq)) * 1024u + h * 64 + qq * 16;
        __half hh[16];
#pragma unroll
        for (int j = 0; j < 16; ++j) hh[j] = __float2half_rn(oa[j] * inv);
        *(uint4*)(dst)     = *(uint4*)(hh);
        *(uint4*)(dst + 8) = *(uint4*)(hh + 8);
    }
}

// ---------------------------------------------------------------------------
// Launch
// ---------------------------------------------------------------------------
extern "C" void kernel_launch(void* const* d_in, const int* in_sizes, int n_in,
                              void* d_out, int out_size)
{
    const float* x     = (const float*)d_in[0];
    const float* Wqkv  = (const float*)d_in[1];
    const float* bqkv  = (const float*)d_in[2];
    const float* Wproj = (const float*)d_in[3];
    const float* bproj = (const float*)d_in[4];
    float* out = (float*)d_out;

    __half *q, *k, *v, *yt, *xh, *wqkvh, *wprojh;
    cudaGetSymbolAddress((void**)&q,  g_q);
    cudaGetSymbolAddress((void**)&k,  g_k);
    cudaGetSymbolAddress((void**)&v,  g_v);
    cudaGetSymbolAddress((void**)&yt, g_yt);
    cudaGetSymbolAddress((void**)&xh, g_xh);
    cudaGetSymbolAddress((void**)&wqkvh, g_wqkvh);
    cudaGetSymbolAddress((void**)&wprojh, g_wprojh);

    const int M = 4096, C = 1024;

    // 0) fp32 -> fp16 conversion passes
    {
        int n8 = (M * C) / 8;
        to_half_kernel<<<(n8 + 255) / 256, 256>>>(x, xh, n8);
        n8 = (C * 3 * C) / 8;
        to_half_kernel<<<(n8 + 255) / 256, 256>>>(Wqkv, wqkvh, n8);
        n8 = (C * C) / 8;
        to_half_kernel<<<(n8 + 255) / 256, 256>>>(Wproj, wprojh, n8);
    }

    cudaFuncSetAttribute(gemm_fp16_kernel<1>,
                         cudaFuncAttributeMaxDynamicSharedMemorySize, G_SMEM_BYTES);
    cudaFuncSetAttribute(gemm_fp16_kernel<0>,
                         cudaFuncAttributeMaxDynamicSharedMemorySize, G_SMEM_BYTES);

    // 1) QKV projection -> half q/k/v
    {
        dim3 grid(3 * C / 128, M / 128);   // (24, 32)
        gemm_fp16_kernel<1><<<grid, 256, G_SMEM_BYTES>>>(xh, wqkvh, bqkv,
                                                         q, k, v, M, 3 * C, C);
    }

    // 2) Flash attention (causal) -> yt (half)
    {
        cudaFuncSetAttribute(flash_fp16_kernel,
                             cudaFuncAttributeMaxDynamicSharedMemorySize, FS_SMEM);
        dim3 grid(2048 / 128, 32);         // (16, 32)
        flash_fp16_kernel<<<grid, 512, FS_SMEM>>>(q, k, v, yt);
    }

    // 3) Output projection -> fp32 out
    {
        dim3 grid(C / 128, M / 128);       // (8, 32)
        gemm_fp16_kernel<0><<<grid, 256, G_SMEM_BYTES>>>(yt, wprojh, bproj,
                                                         out, out, out, M, C, C);
    }
}

// round 10
// speedup vs baseline: 1.5532x; 1.5532x over previous
#include <cuda_runtime.h>
#include <cuda_fp16.h>
#include <mma.h>
#include <cstdint>

namespace wm = nvcuda::wmma;

// ---------------------------------------------------------------------------
// Scratch (device globals)
// ---------------------------------------------------------------------------
__device__ __half g_q [2u * 2048u * 1024u];
__device__ __half g_k [2u * 2048u * 1024u];
__device__ __half g_v [2u * 2048u * 1024u];
__device__ __half g_yt[2u * 2048u * 1024u];
__device__ __half g_xh   [4096u * 1024u];
__device__ __half g_wqkvh[1024u * 3072u];
__device__ __half g_wprojh[1024u * 1024u];

// ---------------------------------------------------------------------------
// cp.async helpers
// ---------------------------------------------------------------------------
__device__ __forceinline__ uint32_t smem_u32(const void* p) {
    return (uint32_t)__cvta_generic_to_shared(p);
}
__device__ __forceinline__ void cp16(uint32_t dst, const void* src) {
    asm volatile("cp.async.cg.shared.global [%0], [%1], 16;"
                 :: "r"(dst), "l"(src) : "memory");
}
__device__ __forceinline__ void cp_commit() {
    asm volatile("cp.async.commit_group;" ::: "memory");
}
template <int N>
__device__ __forceinline__ void cp_wait() {
    asm volatile("cp.async.wait_group %0;" :: "n"(N) : "memory");
}

// ---------------------------------------------------------------------------
// mma / ldmatrix helpers (PTX, documented layouts)
// ---------------------------------------------------------------------------
__device__ __forceinline__ void mma16816(float* c, const uint32_t* a,
                                         uint32_t b0, uint32_t b1) {
    asm volatile(
        "mma.sync.aligned.m16n8k16.row.col.f32.f16.f16.f32 "
        "{%0,%1,%2,%3}, {%4,%5,%6,%7}, {%8,%9}, {%0,%1,%2,%3};"
        : "+f"(c[0]), "+f"(c[1]), "+f"(c[2]), "+f"(c[3])
        : "r"(a[0]), "r"(a[1]), "r"(a[2]), "r"(a[3]), "r"(b0), "r"(b1));
}
__device__ __forceinline__ void ldsm4(uint32_t& r0, uint32_t& r1,
                                      uint32_t& r2, uint32_t& r3, uint32_t a) {
    asm volatile("ldmatrix.sync.aligned.m8n8.x4.shared.b16 {%0,%1,%2,%3}, [%4];"
                 : "=r"(r0), "=r"(r1), "=r"(r2), "=r"(r3) : "r"(a));
}
__device__ __forceinline__ void ldsm4t(uint32_t& r0, uint32_t& r1,
                                       uint32_t& r2, uint32_t& r3, uint32_t a) {
    asm volatile("ldmatrix.sync.aligned.m8n8.x4.trans.shared.b16 {%0,%1,%2,%3}, [%4];"
                 : "=r"(r0), "=r"(r1), "=r"(r2), "=r"(r3) : "r"(a));
}

// ---------------------------------------------------------------------------
// fp32 -> fp16 conversion pass (8 elements/thread)
// ---------------------------------------------------------------------------
__global__ void to_half_kernel(const float* __restrict__ in,
                               __half* __restrict__ out, int n8)
{
    int i = blockIdx.x * blockDim.x + threadIdx.x;
    if (i < n8) {
        float4 a = ((const float4*)in)[i * 2];
        float4 b = ((const float4*)in)[i * 2 + 1];
        __half h[8];
        h[0] = __float2half_rn(a.x); h[1] = __float2half_rn(a.y);
        h[2] = __float2half_rn(a.z); h[3] = __float2half_rn(a.w);
        h[4] = __float2half_rn(b.x); h[5] = __float2half_rn(b.y);
        h[6] = __float2half_rn(b.z); h[7] = __float2half_rn(b.w);
        ((uint4*)out)[i] = *(uint4*)h;
    }
}

// ---------------------------------------------------------------------------
// FP16 WMMA GEMM (fp32 accumulate), 3-stage cp.async, 2 CTAs/SM. (unchanged)
// ---------------------------------------------------------------------------
#define G_ALD 40
#define G_BLD 136
#define G_ASZ (128 * G_ALD)
#define G_BSZ (32 * G_BLD)
#define G_STG 3
#define G_SMEM_BYTES (G_STG * (G_ASZ + G_BSZ) * 2 + 16 * G_BLD * 4)  // 65536

template <int ROUND_OUT>
__global__ __launch_bounds__(256, 2) void gemm_fp16_kernel(
    const __half* __restrict__ A, const __half* __restrict__ B,
    const float* __restrict__ bias,
    void* __restrict__ out0v, void* __restrict__ out1v, void* __restrict__ out2v,
    int M, int N, int K)
{
    extern __shared__ char gsmc[];
    __half* gsm  = (__half*)gsmc;
    float*  Brep = (float*)(gsmc + G_STG * (G_ASZ + G_BSZ) * 2);

    const int tid  = threadIdx.x;
    const int wid  = tid >> 5;
    const int wmi  = wid & 3;
    const int wni  = wid >> 2;
    const int m0   = blockIdx.y * 128;
    const int n0   = blockIdx.x * 128;

    for (int i = tid; i < 16 * 128; i += 256) {
        int r = i >> 7, c = i & 127;
        Brep[r * G_BLD + c] = bias[n0 + c];
    }
    __syncthreads();

    wm::fragment<wm::accumulator, 16, 16, 16, float> acc[2][4];
#pragma unroll
    for (int mi = 0; mi < 2; ++mi)
#pragma unroll
        for (int ni = 0; ni < 4; ++ni)
            wm::load_matrix_sync(acc[mi][ni], Brep + wni * 64 + ni * 16, G_BLD,
                                 wm::mem_row_major);
    __syncthreads();

    const int iters = K >> 5;

    auto issue_stage = [&](int stage) {
        const int s = stage % G_STG;
        const int k0 = stage << 5;
        __half* as = gsm + s * G_ASZ;
        __half* bs = gsm + G_STG * G_ASZ + s * G_BSZ;
#pragma unroll
        for (int t = 0; t < 2; ++t) {
            int f = tid + t * 256;
            int r = f >> 2, c8 = (f & 3) << 3;
            cp16(smem_u32(as + r * G_ALD + c8),
                 A + (size_t)(m0 + r) * K + k0 + c8);
        }
#pragma unroll
        for (int t = 0; t < 2; ++t) {
            int f = tid + t * 256;
            int r = f >> 4, c8 = (f & 15) << 3;
            cp16(smem_u32(bs + r * G_BLD + c8),
                 B + (size_t)(k0 + r) * N + n0 + c8);
        }
        cp_commit();
    };

    issue_stage(0);
    issue_stage(1);

    for (int it = 0; it < iters; ++it) {
        cp_wait<1>();
        __syncthreads();

        if (it + 2 < iters) issue_stage(it + 2);
        else                cp_commit();

        const int s = it % G_STG;
        const __half* as = gsm + s * G_ASZ;
        const __half* bs = gsm + G_STG * G_ASZ + s * G_BSZ;
#pragma unroll
        for (int ks = 0; ks < 2; ++ks) {
            wm::fragment<wm::matrix_a, 16, 16, 16, __half, wm::row_major> af[2];
            wm::fragment<wm::matrix_b, 16, 16, 16, __half, wm::row_major> bf[4];
#pragma unroll
            for (int mi = 0; mi < 2; ++mi)
                wm::load_matrix_sync(af[mi], as + (wmi * 32 + mi * 16) * G_ALD + ks * 16, G_ALD);
#pragma unroll
            for (int ni = 0; ni < 4; ++ni)
                wm::load_matrix_sync(bf[ni], bs + (ks * 16) * G_BLD + wni * 64 + ni * 16, G_BLD);
#pragma unroll
            for (int mi = 0; mi < 2; ++mi)
#pragma unroll
                for (int ni = 0; ni < 4; ++ni)
                    wm::mma_sync(acc[mi][ni], af[mi], bf[ni], acc[mi][ni]);
        }
        __syncthreads();
    }

    const int nc = n0 & 1023;
    if (ROUND_OUT) {
        __half* outp = (n0 < 1024) ? (__half*)out0v
                     : ((n0 < 2048) ? (__half*)out1v : (__half*)out2v);
        float* stg = (float*)gsmc;
#pragma unroll
        for (int mi = 0; mi < 2; ++mi) {
            __syncthreads();
#pragma unroll
            for (int ni = 0; ni < 4; ++ni)
                wm::store_matrix_sync(stg + (wmi * 16) * G_BLD + wni * 64 + ni * 16,
                                      acc[mi][ni], G_BLD, wm::mem_row_major);
            __syncthreads();
#pragma unroll
            for (int t = 0; t < 4; ++t) {
                int idx = tid + t * 256;
                int sr = idx >> 4;
                int c8 = (idx & 15) << 3;
                int grow = m0 + (sr >> 4) * 32 + mi * 16 + (sr & 15);
                const float* s = stg + sr * G_BLD + c8;
                __half h[8];
#pragma unroll
                for (int j = 0; j < 8; ++j) h[j] = __float2half_rn(s[j]);
                *(uint4*)(outp + (size_t)grow * 1024 + nc + c8) = *(uint4*)h;
            }
        }
    } else {
        float* outp = (n0 < 1024) ? (float*)out0v
                    : ((n0 < 2048) ? (float*)out1v : (float*)out2v);
#pragma unroll
        for (int mi = 0; mi < 2; ++mi)
#pragma unroll
            for (int ni = 0; ni < 4; ++ni) {
                float* p = outp + (size_t)(m0 + wmi * 32 + mi * 16) * 1024
                                + nc + wni * 64 + ni * 16;
                wm::store_matrix_sync(p, acc[mi][ni], 1024, wm::mem_row_major);
            }
    }
}

// ---------------------------------------------------------------------------
// Flash attention (causal), FA2-style PTX mma. Br=128, Bc=64, hd=64, 256 thr.
// 8 warps x 16 rows. Q/S/P/O all register-resident; only K/V in smem
// (cp.async double-buffered, ldmatrix / ldmatrix.trans). 1 barrier per iter.
// ---------------------------------------------------------------------------
#define FLD 72            // smem leading dim in halves (144B rows, conflict-free)
#define FQ_OFF 0          // Q: 128 x FLD halves = 18432 B
#define FK0_OFF 18432     // K/V: 64 x FLD halves = 9216 B each
#define FK1_OFF 27648
#define FV0_OFF 36864
#define FV1_OFF 46080
#define F_SMEM  55296

__global__ __launch_bounds__(256) void flash_fa2_kernel(
    const __half* __restrict__ Qg, const __half* __restrict__ Kg,
    const __half* __restrict__ Vg, __half* __restrict__ yt)
{
    extern __shared__ char smc[];
    __half* Qs = (__half*)(smc + FQ_OFF);
    const uint32_t smb = smem_u32(smc);
    const uint32_t kbA[2] = { smb + FK0_OFF, smb + FK1_OFF };
    const uint32_t vbA[2] = { smb + FV0_OFF, smb + FV1_OFF };

    const int qt   = gridDim.x - 1 - blockIdx.x;   // longest-first
    const int bh   = blockIdx.y;
    const int tid  = threadIdx.x;
    const int w    = tid >> 5;
    const int lane = tid & 31;

    // ldmatrix per-lane address components
    const int q_row = (lane & 15);                 // + 8*(lane>>4) col
    const int q_col = (lane >> 4) << 3;
    const int k_row = (lane & 7) + ((lane >> 4) << 3);
    const int k_col = ((lane >> 3) & 1) << 3;
    const int v_row = (lane & 7) + (((lane >> 3) & 1) << 3);
    const int v_col = (lane >> 4) << 3;

    const size_t head_off = (size_t)bh * 131072u;
    const __half* qg = Qg + head_off + (size_t)qt * 8192u;
    const __half* kg = Kg + head_off;
    const __half* vg = Vg + head_off;

    auto issue_kv = [&](int kt, int buf) {
        const __half* kp = kg + (size_t)kt * 4096u;
        const __half* vp = vg + (size_t)kt * 4096u;
#pragma unroll
        for (int t = 0; t < 2; ++t) {
            int f = tid + t * 256;
            int rr = f >> 3, c8 = (f & 7) << 3;
            cp16(kbA[buf] + (rr * FLD + c8) * 2, kp + rr * 64 + c8);
            cp16(vbA[buf] + (rr * FLD + c8) * 2, vp + rr * 64 + c8);
        }
        cp_commit();
    };

    issue_kv(0, 0);

    // Stage Q -> smem (scaled by 0.125, exact in fp16)
    const __half2 sc = __half2half2(__float2half_rn(0.125f));
#pragma unroll
    for (int t = 0; t < 4; ++t) {
        int f = tid + t * 256;
        int rr = f >> 3, c8 = (f & 7) << 3;
        uint4 raw = *(const uint4*)(qg + rr * 64 + c8);
        __half2* hp = (__half2*)&raw;
#pragma unroll
        for (int j = 0; j < 4; ++j) hp[j] = __hmul2(hp[j], sc);
        *(uint4*)(Qs + rr * FLD + c8) = raw;
    }
    __syncthreads();

    // Q fragments (register-resident for whole kernel): 4 k-tiles x 4 regs
    uint32_t qf[4][4];
#pragma unroll
    for (int kk = 0; kk < 4; ++kk) {
        uint32_t a = smb + FQ_OFF
                   + ((w * 16 + q_row) * FLD + kk * 16 + q_col) * 2;
        ldsm4(qf[kk][0], qf[kk][1], qf[kk][2], qf[kk][3], a);
    }

    float oacc[8][4];
#pragma unroll
    for (int nt = 0; nt < 8; ++nt)
#pragma unroll
        for (int j = 0; j < 4; ++j) oacc[nt][j] = 0.0f;
    float m_lo = -1e30f, m_hi = -1e30f;
    float l_lo = 0.0f,   l_hi = 0.0f;

    int buf = 0;
    const int n_kt = 2 * (qt + 1);
    const int row_g_lo = qt * 128 + w * 16 + (lane >> 2);
    const int row_g_hi = row_g_lo + 8;

    for (int kt = 0; kt < n_kt; ++kt) {
        cp_wait<0>();
        __syncthreads();
        if (kt + 1 < n_kt) issue_kv(kt + 1, buf ^ 1);

        // ---- S = Q @ K^T : 8 n-tiles x 4 k-tiles ----
        float sacc[8][4];
#pragma unroll
        for (int nt = 0; nt < 8; ++nt)
#pragma unroll
            for (int j = 0; j < 4; ++j) sacc[nt][j] = 0.0f;
#pragma unroll
        for (int p = 0; p < 4; ++p) {
#pragma unroll
            for (int kk = 0; kk < 4; ++kk) {
                uint32_t b0, b1, b2, b3;
                uint32_t a = kbA[buf]
                           + ((p * 16 + k_row) * FLD + kk * 16 + k_col) * 2;
                ldsm4(b0, b1, b2, b3, a);
                mma16816(sacc[2 * p],     qf[kk], b0, b1);
                mma16816(sacc[2 * p + 1], qf[kk], b2, b3);
            }
        }

        // ---- causal mask (only near the diagonal) ----
        if (kt >= 2 * qt) {
            const int cb = kt * 64 + 2 * (lane & 3);
#pragma unroll
            for (int nt = 0; nt < 8; ++nt) {
                int c = cb + nt * 8;
                if (c     > row_g_lo) sacc[nt][0] = -1e30f;
                if (c + 1 > row_g_lo) sacc[nt][1] = -1e30f;
                if (c     > row_g_hi) sacc[nt][2] = -1e30f;
                if (c + 1 > row_g_hi) sacc[nt][3] = -1e30f;
            }
        }

        // ---- online softmax in registers ----
        float mx_lo = -1e30f, mx_hi = -1e30f;
#pragma unroll
        for (int nt = 0; nt < 8; ++nt) {
            mx_lo = fmaxf(mx_lo, fmaxf(sacc[nt][0], sacc[nt][1]));
            mx_hi = fmaxf(mx_hi, fmaxf(sacc[nt][2], sacc[nt][3]));
        }
        mx_lo = fmaxf(mx_lo, __shfl_xor_sync(0xffffffffu, mx_lo, 1));
        mx_lo = fmaxf(mx_lo, __shfl_xor_sync(0xffffffffu, mx_lo, 2));
        mx_hi = fmaxf(mx_hi, __shfl_xor_sync(0xffffffffu, mx_hi, 1));
        mx_hi = fmaxf(mx_hi, __shfl_xor_sync(0xffffffffu, mx_hi, 2));

        const float mn_lo = fmaxf(m_lo, mx_lo);
        const float mn_hi = fmaxf(m_hi, mx_hi);
        const float al_lo = __expf(m_lo - mn_lo);
        const float al_hi = __expf(m_hi - mn_hi);
        m_lo = mn_lo; m_hi = mn_hi;

        float sum_lo = 0.0f, sum_hi = 0.0f;
        uint32_t pfr[4][4];
#pragma unroll
        for (int nt = 0; nt < 8; ++nt) {
            float p0 = __expf(sacc[nt][0] - mn_lo);
            float p1 = __expf(sacc[nt][1] - mn_lo);
            float p2 = __expf(sacc[nt][2] - mn_hi);
            float p3 = __expf(sacc[nt][3] - mn_hi);
            sum_lo += p0 + p1;
            sum_hi += p2 + p3;
            __half2 h01 = __floats2half2_rn(p0, p1);
            __half2 h23 = __floats2half2_rn(p2, p3);
            pfr[nt >> 1][(nt & 1) * 2 + 0] = *(uint32_t*)&h01;
            pfr[nt >> 1][(nt & 1) * 2 + 1] = *(uint32_t*)&h23;
        }
        l_lo = l_lo * al_lo + sum_lo;    // per-lane partial; reduced at end
        l_hi = l_hi * al_hi + sum_hi;

        // rescale O accumulators
#pragma unroll
        for (int nt = 0; nt < 8; ++nt) {
            oacc[nt][0] *= al_lo; oacc[nt][1] *= al_lo;
            oacc[nt][2] *= al_hi; oacc[nt][3] *= al_hi;
        }

        // ---- O += P @ V : 4 n-pairs x 4 k-tiles ----
#pragma unroll
        for (int p = 0; p < 4; ++p) {
#pragma unroll
            for (int t = 0; t < 4; ++t) {
                uint32_t b0, b1, b2, b3;
                uint32_t a = vbA[buf]
                           + ((t * 16 + v_row) * FLD + p * 16 + v_col) * 2;
                ldsm4t(b0, b1, b2, b3, a);
                mma16816(oacc[2 * p],     pfr[t], b0, b1);
                mma16816(oacc[2 * p + 1], pfr[t], b2, b3);
            }
        }
        buf ^= 1;
    }

    // ---- Epilogue: reduce l across the 4 col-lanes, normalize, store ----
    l_lo += __shfl_xor_sync(0xffffffffu, l_lo, 1);
    l_lo += __shfl_xor_sync(0xffffffffu, l_lo, 2);
    l_hi += __shfl_xor_sync(0xffffffffu, l_hi, 1);
    l_hi += __shfl_xor_sync(0xffffffffu, l_hi, 2);
    const float inv_lo = 1.0f / l_lo;
    const float inv_hi = 1.0f / l_hi;

    const int b = bh >> 4;
    const int h = bh & 15;
    const int tq_lo = qt * 128 + w * 16 + (lane >> 2);
    __half* dst_lo = yt + ((size_t)(b * 2048 + tq_lo)) * 1024u + h * 64 + 2 * (lane & 3);
    __half* dst_hi = dst_lo + 8u * 1024u;
#pragma unroll
    for (int nt = 0; nt < 8; ++nt) {
        __half2 vlo = __floats2half2_rn(oacc[nt][0] * inv_lo, oacc[nt][1] * inv_lo);
        __half2 vhi = __floats2half2_rn(oacc[nt][2] * inv_hi, oacc[nt][3] * inv_hi);
        *(__half2*)(dst_lo + nt * 8) = vlo;
        *(__half2*)(dst_hi + nt * 8) = vhi;
    }
}

// ---------------------------------------------------------------------------
// Launch
// ---------------------------------------------------------------------------
extern "C" void kernel_launch(void* const* d_in, const int* in_sizes, int n_in,
                              void* d_out, int out_size)
{
    const float* x     = (const float*)d_in[0];
    const float* Wqkv  = (const float*)d_in[1];
    const float* bqkv  = (const float*)d_in[2];
    const float* Wproj = (const float*)d_in[3];
    const float* bproj = (const float*)d_in[4];
    float* out = (float*)d_out;

    __half *q, *k, *v, *yt, *xh, *wqkvh, *wprojh;
    cudaGetSymbolAddress((void**)&q,  g_q);
    cudaGetSymbolAddress((void**)&k,  g_k);
    cudaGetSymbolAddress((void**)&v,  g_v);
    cudaGetSymbolAddress((void**)&yt, g_yt);
    cudaGetSymbolAddress((void**)&xh, g_xh);
    cudaGetSymbolAddress((void**)&wqkvh, g_wqkvh);
    cudaGetSymbolAddress((void**)&wprojh, g_wprojh);

    const int M = 4096, C = 1024;

    // 0) fp32 -> fp16 conversion passes
    {
        int n8 = (M * C) / 8;
        to_half_kernel<<<(n8 + 255) / 256, 256>>>(x, xh, n8);
        n8 = (C * 3 * C) / 8;
        to_half_kernel<<<(n8 + 255) / 256, 256>>>(Wqkv, wqkvh, n8);
        n8 = (C * C) / 8;
        to_half_kernel<<<(n8 + 255) / 256, 256>>>(Wproj, wprojh, n8);
    }

    cudaFuncSetAttribute(gemm_fp16_kernel<1>,
                         cudaFuncAttributeMaxDynamicSharedMemorySize, G_SMEM_BYTES);
    cudaFuncSetAttribute(gemm_fp16_kernel<0>,
                         cudaFuncAttributeMaxDynamicSharedMemorySize, G_SMEM_BYTES);

    // 1) QKV projection -> half q/k/v
    {
        dim3 grid(3 * C / 128, M / 128);   // (24, 32)
        gemm_fp16_kernel<1><<<grid, 256, G_SMEM_BYTES>>>(xh, wqkvh, bqkv,
                                                         q, k, v, M, 3 * C, C);
    }

    // 2) Flash attention (causal) -> yt (half), FA2 register-resident
    {
        cudaFuncSetAttribute(flash_fa2_kernel,
                             cudaFuncAttributeMaxDynamicSharedMemorySize, F_SMEM);
        dim3 grid(2048 / 128, 32);         // (16, 32)
        flash_fa2_kernel<<<grid, 256, F_SMEM>>>(q, k, v, yt);
    }

    // 3) Output projection -> fp32 out
    {
        dim3 grid(C / 128, M / 128);       // (8, 32)
        gemm_fp16_kernel<0><<<grid, 256, G_SMEM_BYTES>>>(yt, wprojh, bproj,
                                                         out, out, out, M, C, C);
    }
}

// round 11
// speedup vs baseline: 1.5668x; 1.0088x over previous
#include <cuda_runtime.h>
#include <cuda_fp16.h>
#include <cstdint>

// ---------------------------------------------------------------------------
// Scratch (device globals)
// ---------------------------------------------------------------------------
__device__ __half g_q [2u * 2048u * 1024u];
__device__ __half g_k [2u * 2048u * 1024u];
__device__ __half g_v [2u * 2048u * 1024u];
__device__ __half g_yt[2u * 2048u * 1024u];
__device__ __half g_xh   [4096u * 1024u];
__device__ __half g_wqkvh[1024u * 3072u];
__device__ __half g_wprojh[1024u * 1024u];

// ---------------------------------------------------------------------------
// cp.async helpers
// ---------------------------------------------------------------------------
__device__ __forceinline__ uint32_t smem_u32(const void* p) {
    return (uint32_t)__cvta_generic_to_shared(p);
}
__device__ __forceinline__ void cp16(uint32_t dst, const void* src) {
    asm volatile("cp.async.cg.shared.global [%0], [%1], 16;"
                 :: "r"(dst), "l"(src) : "memory");
}
__device__ __forceinline__ void cp_commit() {
    asm volatile("cp.async.commit_group;" ::: "memory");
}
template <int N>
__device__ __forceinline__ void cp_wait() {
    asm volatile("cp.async.wait_group %0;" :: "n"(N) : "memory");
}

// ---------------------------------------------------------------------------
// mma / ldmatrix helpers
// ---------------------------------------------------------------------------
__device__ __forceinline__ void mma16816(float* c, const uint32_t* a,
                                         uint32_t b0, uint32_t b1) {
    asm volatile(
        "mma.sync.aligned.m16n8k16.row.col.f32.f16.f16.f32 "
        "{%0,%1,%2,%3}, {%4,%5,%6,%7}, {%8,%9}, {%0,%1,%2,%3};"
        : "+f"(c[0]), "+f"(c[1]), "+f"(c[2]), "+f"(c[3])
        : "r"(a[0]), "r"(a[1]), "r"(a[2]), "r"(a[3]), "r"(b0), "r"(b1));
}
__device__ __forceinline__ void ldsm4(uint32_t& r0, uint32_t& r1,
                                      uint32_t& r2, uint32_t& r3, uint32_t a) {
    asm volatile("ldmatrix.sync.aligned.m8n8.x4.shared.b16 {%0,%1,%2,%3}, [%4];"
                 : "=r"(r0), "=r"(r1), "=r"(r2), "=r"(r3) : "r"(a));
}
__device__ __forceinline__ void ldsm4t(uint32_t& r0, uint32_t& r1,
                                       uint32_t& r2, uint32_t& r3, uint32_t a) {
    asm volatile("ldmatrix.sync.aligned.m8n8.x4.trans.shared.b16 {%0,%1,%2,%3}, [%4];"
                 : "=r"(r0), "=r"(r1), "=r"(r2), "=r"(r3) : "r"(a));
}

// ---------------------------------------------------------------------------
// Combined fp32 -> fp16 conversion (x, Wqkv, Wproj in one launch)
// ---------------------------------------------------------------------------
#define N8_X  (4096u * 1024u / 8u)      // 524288
#define N8_WQ (1024u * 3072u / 8u)      // 393216
#define N8_WP (1024u * 1024u / 8u)      // 131072

__global__ void to_half3_kernel(const float* __restrict__ x,
                                const float* __restrict__ wq,
                                const float* __restrict__ wp,
                                __half* __restrict__ xh,
                                __half* __restrict__ wqh,
                                __half* __restrict__ wph)
{
    uint32_t i = blockIdx.x * blockDim.x + threadIdx.x;
    const float* in;
    __half* out;
    uint32_t j;
    if (i < N8_X)                { in = x;  out = xh;  j = i; }
    else if (i < N8_X + N8_WQ)   { in = wq; out = wqh; j = i - N8_X; }
    else if (i < N8_X + N8_WQ + N8_WP) { in = wp; out = wph; j = i - N8_X - N8_WQ; }
    else return;
    float4 a = ((const float4*)in)[j * 2];
    float4 b = ((const float4*)in)[j * 2 + 1];
    __half h[8];
    h[0] = __float2half_rn(a.x); h[1] = __float2half_rn(a.y);
    h[2] = __float2half_rn(a.z); h[3] = __float2half_rn(a.w);
    h[4] = __float2half_rn(b.x); h[5] = __float2half_rn(b.y);
    h[6] = __float2half_rn(b.z); h[7] = __float2half_rn(b.w);
    ((uint4*)out)[j] = *(uint4*)h;
}

// ---------------------------------------------------------------------------
// FP16 raw-mma GEMM (fp32 accumulate), 3-stage cp.async, 2 CTAs/SM.
// C = A[M,K] @ B[K,N] + bias[N]. BM=BN=128, BK=32, 256 thr (8 warps 4x2),
// warp tile 32x64 via mma.m16n8k16 + ldmatrix. One barrier per K-step.
// ROUND_OUT=1: store half; 0: store fp32. Output routed into 3 buffers.
// ---------------------------------------------------------------------------
#define G_ALD 40
#define G_BLD 136
#define G_ASZ (128 * G_ALD)   // halves per A stage
#define G_BSZ (32 * G_BLD)    // halves per B stage
#define G_STG 3
#define G_SMEM_BYTES (G_STG * (G_ASZ + G_BSZ) * 2)   // 56832

template <int ROUND_OUT>
__global__ __launch_bounds__(256, 2) void gemm_mma_kernel(
    const __half* __restrict__ A, const __half* __restrict__ B,
    const float* __restrict__ bias,
    void* __restrict__ out0v, void* __restrict__ out1v, void* __restrict__ out2v,
    int M, int N, int K)
{
    extern __shared__ char gsmc[];
    __half* gsm = (__half*)gsmc;
    const uint32_t smb = smem_u32(gsmc);

    const int tid  = threadIdx.x;
    const int wid  = tid >> 5;
    const int lane = tid & 31;
    const int wmi  = wid & 3;        // 32-row stripe
    const int wni  = wid >> 2;       // 64-col stripe
    const int m0   = blockIdx.y * 128;
    const int n0   = blockIdx.x * 128;

    // ldmatrix lane-address components
    const int a_row = (lane & 15);
    const int a_col = (lane >> 4) << 3;
    const int b_row = (lane & 7) + (((lane >> 3) & 1) << 3);   // k within 16
    const int b_col = (lane >> 4) << 3;                        // n offset 0/8

    float cfr[2][8][4];
#pragma unroll
    for (int mi = 0; mi < 2; ++mi)
#pragma unroll
        for (int nt = 0; nt < 8; ++nt)
#pragma unroll
            for (int j = 0; j < 4; ++j) cfr[mi][nt][j] = 0.0f;

    const int iters = K >> 5;

    auto issue_stage = [&](int stage) {
        const int s = stage % G_STG;
        const int k0 = stage << 5;
        __half* as = gsm + s * G_ASZ;
        __half* bs = gsm + G_STG * G_ASZ + s * G_BSZ;
#pragma unroll
        for (int t = 0; t < 2; ++t) {
            int f = tid + t * 256;
            int r = f >> 2, c8 = (f & 3) << 3;
            cp16(smem_u32(as + r * G_ALD + c8),
                 A + (size_t)(m0 + r) * K + k0 + c8);
        }
#pragma unroll
        for (int t = 0; t < 2; ++t) {
            int f = tid + t * 256;
            int r = f >> 4, c8 = (f & 15) << 3;
            cp16(smem_u32(bs + r * G_BLD + c8),
                 B + (size_t)(k0 + r) * N + n0 + c8);
        }
        cp_commit();
    };

    issue_stage(0);
    issue_stage(1);

    for (int it = 0; it < iters; ++it) {
        cp_wait<1>();
        __syncthreads();

        if (it + 2 < iters) issue_stage(it + 2);
        else                cp_commit();

        const int s = it % G_STG;
        const uint32_t a_base = smb + (s * G_ASZ
                              + (wmi * 32 + a_row) * G_ALD + a_col) * 2;
        const uint32_t b_base = smb + (G_STG * G_ASZ + s * G_BSZ
                              + b_row * G_BLD + wni * 64 + b_col) * 2;

#pragma unroll
        for (int ks = 0; ks < 2; ++ks) {
            uint32_t af[2][4];
#pragma unroll
            for (int mi = 0; mi < 2; ++mi)
                ldsm4(af[mi][0], af[mi][1], af[mi][2], af[mi][3],
                      a_base + (mi * 16 * G_ALD + ks * 16) * 2);
            uint32_t bf[4][4];
#pragma unroll
            for (int p = 0; p < 4; ++p)
                ldsm4t(bf[p][0], bf[p][1], bf[p][2], bf[p][3],
                       b_base + (ks * 16 * G_BLD + p * 16) * 2);
#pragma unroll
            for (int mi = 0; mi < 2; ++mi)
#pragma unroll
                for (int p = 0; p < 4; ++p) {
                    mma16816(cfr[mi][2 * p],     af[mi], bf[p][0], bf[p][1]);
                    mma16816(cfr[mi][2 * p + 1], af[mi], bf[p][2], bf[p][3]);
                }
        }
    }

    // ---- Epilogue: bias + store ----
    const int nc = n0 & 1023;
    const int colw = wni * 64 + 2 * (lane & 3);
    float2 bv[8];
#pragma unroll
    for (int nt = 0; nt < 8; ++nt) {
        bv[nt].x = bias[n0 + colw + nt * 8];
        bv[nt].y = bias[n0 + colw + nt * 8 + 1];
    }
    const int row0 = m0 + wmi * 32 + (lane >> 2);

    if (ROUND_OUT) {
        __half* outp = (n0 < 1024) ? (__half*)out0v
                     : ((n0 < 2048) ? (__half*)out1v : (__half*)out2v);
#pragma unroll
        for (int mi = 0; mi < 2; ++mi) {
#pragma unroll
            for (int nt = 0; nt < 8; ++nt) {
                int col = nc + colw + nt * 8;
                __half2 v0 = __floats2half2_rn(cfr[mi][nt][0] + bv[nt].x,
                                               cfr[mi][nt][1] + bv[nt].y);
                __half2 v1 = __floats2half2_rn(cfr[mi][nt][2] + bv[nt].x,
                                               cfr[mi][nt][3] + bv[nt].y);
                *(__half2*)(outp + (size_t)(row0 + mi * 16) * 1024 + col) = v0;
                *(__half2*)(outp + (size_t)(row0 + mi * 16 + 8) * 1024 + col) = v1;
            }
        }
    } else {
        float* outp = (n0 < 1024) ? (float*)out0v
                    : ((n0 < 2048) ? (float*)out1v : (float*)out2v);
#pragma unroll
        for (int mi = 0; mi < 2; ++mi) {
#pragma unroll
            for (int nt = 0; nt < 8; ++nt) {
                int col = nc + colw + nt * 8;
                float2 v0 = { cfr[mi][nt][0] + bv[nt].x, cfr[mi][nt][1] + bv[nt].y };
                float2 v1 = { cfr[mi][nt][2] + bv[nt].x, cfr[mi][nt][3] + bv[nt].y };
                *(float2*)(outp + (size_t)(row0 + mi * 16) * 1024 + col) = v0;
                *(float2*)(outp + (size_t)(row0 + mi * 16 + 8) * 1024 + col) = v1;
            }
        }
    }
}

// ---------------------------------------------------------------------------
// Flash attention (causal), FA2-style PTX mma. Br=128, Bc=64, hd=64, 256 thr.
// (unchanged from round 10 — register-resident S/P/O)
// ---------------------------------------------------------------------------
#define FLD 72
#define FQ_OFF 0
#define FK0_OFF 18432
#define FK1_OFF 27648
#define FV0_OFF 36864
#define FV1_OFF 46080
#define F_SMEM  55296

__global__ __launch_bounds__(256) void flash_fa2_kernel(
    const __half* __restrict__ Qg, const __half* __restrict__ Kg,
    const __half* __restrict__ Vg, __half* __restrict__ yt)
{
    extern __shared__ char smc[];
    __half* Qs = (__half*)(smc + FQ_OFF);
    const uint32_t smb = smem_u32(smc);
    const uint32_t kbA[2] = { smb + FK0_OFF, smb + FK1_OFF };
    const uint32_t vbA[2] = { smb + FV0_OFF, smb + FV1_OFF };

    const int qt   = gridDim.x - 1 - blockIdx.x;
    const int bh   = blockIdx.y;
    const int tid  = threadIdx.x;
    const int w    = tid >> 5;
    const int lane = tid & 31;

    const int q_row = (lane & 15);
    const int q_col = (lane >> 4) << 3;
    const int k_row = (lane & 7) + ((lane >> 4) << 3);
    const int k_col = ((lane >> 3) & 1) << 3;
    const int v_row = (lane & 7) + (((lane >> 3) & 1) << 3);
    const int v_col = (lane >> 4) << 3;

    const size_t head_off = (size_t)bh * 131072u;
    const __half* qg = Qg + head_off + (size_t)qt * 8192u;
    const __half* kg = Kg + head_off;
    const __half* vg = Vg + head_off;

    auto issue_kv = [&](int kt, int buf) {
        const __half* kp = kg + (size_t)kt * 4096u;
        const __half* vp = vg + (size_t)kt * 4096u;
#pragma unroll
        for (int t = 0; t < 2; ++t) {
            int f = tid + t * 256;
            int rr = f >> 3, c8 = (f & 7) << 3;
            cp16(kbA[buf] + (rr * FLD + c8) * 2, kp + rr * 64 + c8);
            cp16(vbA[buf] + (rr * FLD + c8) * 2, vp + rr * 64 + c8);
        }
        cp_commit();
    };

    issue_kv(0, 0);

    const __half2 sc = __half2half2(__float2half_rn(0.125f));
#pragma unroll
    for (int t = 0; t < 4; ++t) {
        int f = tid + t * 256;
        int rr = f >> 3, c8 = (f & 7) << 3;
        uint4 raw = *(const uint4*)(qg + rr * 64 + c8);
        __half2* hp = (__half2*)&raw;
#pragma unroll
        for (int j = 0; j < 4; ++j) hp[j] = __hmul2(hp[j], sc);
        *(uint4*)(Qs + rr * FLD + c8) = raw;
    }
    __syncthreads();

    uint32_t qf[4][4];
#pragma unroll
    for (int kk = 0; kk < 4; ++kk) {
        uint32_t a = smb + FQ_OFF
                   + ((w * 16 + q_row) * FLD + kk * 16 + q_col) * 2;
        ldsm4(qf[kk][0], qf[kk][1], qf[kk][2], qf[kk][3], a);
    }

    float oacc[8][4];
#pragma unroll
    for (int nt = 0; nt < 8; ++nt)
#pragma unroll
        for (int j = 0; j < 4; ++j) oacc[nt][j] = 0.0f;
    float m_lo = -1e30f, m_hi = -1e30f;
    float l_lo = 0.0f,   l_hi = 0.0f;

    int buf = 0;
    const int n_kt = 2 * (qt + 1);
    const int row_g_lo = qt * 128 + w * 16 + (lane >> 2);
    const int row_g_hi = row_g_lo + 8;

    for (int kt = 0; kt < n_kt; ++kt) {
        cp_wait<0>();
        __syncthreads();
        if (kt + 1 < n_kt) issue_kv(kt + 1, buf ^ 1);

        float sacc[8][4];
#pragma unroll
        for (int nt = 0; nt < 8; ++nt)
#pragma unroll
            for (int j = 0; j < 4; ++j) sacc[nt][j] = 0.0f;
#pragma unroll
        for (int p = 0; p < 4; ++p) {
#pragma unroll
            for (int kk = 0; kk < 4; ++kk) {
                uint32_t b0, b1, b2, b3;
                uint32_t a = kbA[buf]
                           + ((p * 16 + k_row) * FLD + kk * 16 + k_col) * 2;
                ldsm4(b0, b1, b2, b3, a);
                mma16816(sacc[2 * p],     qf[kk], b0, b1);
                mma16816(sacc[2 * p + 1], qf[kk], b2, b3);
            }
        }

        if (kt >= 2 * qt) {
            const int cb = kt * 64 + 2 * (lane & 3);
#pragma unroll
            for (int nt = 0; nt < 8; ++nt) {
                int c = cb + nt * 8;
                if (c     > row_g_lo) sacc[nt][0] = -1e30f;
                if (c + 1 > row_g_lo) sacc[nt][1] = -1e30f;
                if (c     > row_g_hi) sacc[nt][2] = -1e30f;
                if (c + 1 > row_g_hi) sacc[nt][3] = -1e30f;
            }
        }

        float mx_lo = -1e30f, mx_hi = -1e30f;
#pragma unroll
        for (int nt = 0; nt < 8; ++nt) {
            mx_lo = fmaxf(mx_lo, fmaxf(sacc[nt][0], sacc[nt][1]));
            mx_hi = fmaxf(mx_hi, fmaxf(sacc[nt][2], sacc[nt][3]));
        }
        mx_lo = fmaxf(mx_lo, __shfl_xor_sync(0xffffffffu, mx_lo, 1));
        mx_lo = fmaxf(mx_lo, __shfl_xor_sync(0xffffffffu, mx_lo, 2));
        mx_hi = fmaxf(mx_hi, __shfl_xor_sync(0xffffffffu, mx_hi, 1));
        mx_hi = fmaxf(mx_hi, __shfl_xor_sync(0xffffffffu, mx_hi, 2));

        const float mn_lo = fmaxf(m_lo, mx_lo);
        const float mn_hi = fmaxf(m_hi, mx_hi);
        const float al_lo = __expf(m_lo - mn_lo);
        const float al_hi = __expf(m_hi - mn_hi);
        m_lo = mn_lo; m_hi = mn_hi;

        float sum_lo = 0.0f, sum_hi = 0.0f;
        uint32_t pfr[4][4];
#pragma unroll
        for (int nt = 0; nt < 8; ++nt) {
            float p0 = __expf(sacc[nt][0] - mn_lo);
            float p1 = __expf(sacc[nt][1] - mn_lo);
            float p2 = __expf(sacc[nt][2] - mn_hi);
            float p3 = __expf(sacc[nt][3] - mn_hi);
            sum_lo += p0 + p1;
            sum_hi += p2 + p3;
            __half2 h01 = __floats2half2_rn(p0, p1);
            __half2 h23 = __floats2half2_rn(p2, p3);
            pfr[nt >> 1][(nt & 1) * 2 + 0] = *(uint32_t*)&h01;
            pfr[nt >> 1][(nt & 1) * 2 + 1] = *(uint32_t*)&h23;
        }
        l_lo = l_lo * al_lo + sum_lo;
        l_hi = l_hi * al_hi + sum_hi;

#pragma unroll
        for (int nt = 0; nt < 8; ++nt) {
            oacc[nt][0] *= al_lo; oacc[nt][1] *= al_lo;
            oacc[nt][2] *= al_hi; oacc[nt][3] *= al_hi;
        }

#pragma unroll
        for (int p = 0; p < 4; ++p) {
#pragma unroll
            for (int t = 0; t < 4; ++t) {
                uint32_t b0, b1, b2, b3;
                uint32_t a = vbA[buf]
                           + ((t * 16 + v_row) * FLD + p * 16 + v_col) * 2;
                ldsm4t(b0, b1, b2, b3, a);
                mma16816(oacc[2 * p],     pfr[t], b0, b1);
                mma16816(oacc[2 * p + 1], pfr[t], b2, b3);
            }
        }
        buf ^= 1;
    }

    l_lo += __shfl_xor_sync(0xffffffffu, l_lo, 1);
    l_lo += __shfl_xor_sync(0xffffffffu, l_lo, 2);
    l_hi += __shfl_xor_sync(0xffffffffu, l_hi, 1);
    l_hi += __shfl_xor_sync(0xffffffffu, l_hi, 2);
    const float inv_lo = 1.0f / l_lo;
    const float inv_hi = 1.0f / l_hi;

    const int b = bh >> 4;
    const int h = bh & 15;
    const int tq_lo = qt * 128 + w * 16 + (lane >> 2);
    __half* dst_lo = yt + ((size_t)(b * 2048 + tq_lo)) * 1024u + h * 64 + 2 * (lane & 3);
    __half* dst_hi = dst_lo + 8u * 1024u;
#pragma unroll
    for (int nt = 0; nt < 8; ++nt) {
        __half2 vlo = __floats2half2_rn(oacc[nt][0] * inv_lo, oacc[nt][1] * inv_lo);
        __half2 vhi = __floats2half2_rn(oacc[nt][2] * inv_hi, oacc[nt][3] * inv_hi);
        *(__half2*)(dst_lo + nt * 8) = vlo;
        *(__half2*)(dst_hi + nt * 8) = vhi;
    }
}

// ---------------------------------------------------------------------------
// Launch
// ---------------------------------------------------------------------------
extern "C" void kernel_launch(void* const* d_in, const int* in_sizes, int n_in,
                              void* d_out, int out_size)
{
    const float* x     = (const float*)d_in[0];
    const float* Wqkv  = (const float*)d_in[1];
    const float* bqkv  = (const float*)d_in[2];
    const float* Wproj = (const float*)d_in[3];
    const float* bproj = (const float*)d_in[4];
    float* out = (float*)d_out;

    __half *q, *k, *v, *yt, *xh, *wqkvh, *wprojh;
    cudaGetSymbolAddress((void**)&q,  g_q);
    cudaGetSymbolAddress((void**)&k,  g_k);
    cudaGetSymbolAddress((void**)&v,  g_v);
    cudaGetSymbolAddress((void**)&yt, g_yt);
    cudaGetSymbolAddress((void**)&xh, g_xh);
    cudaGetSymbolAddress((void**)&wqkvh, g_wqkvh);
    cudaGetSymbolAddress((void**)&wprojh, g_wprojh);

    const int M = 4096, C = 1024;

    // 0) fp32 -> fp16 conversion (single launch)
    {
        uint32_t total = N8_X + N8_WQ + N8_WP;   // 1048576
        to_half3_kernel<<<(total + 255) / 256, 256>>>(x, Wqkv, Wproj,
                                                      xh, wqkvh, wprojh);
    }

    cudaFuncSetAttribute(gemm_mma_kernel<1>,
                         cudaFuncAttributeMaxDynamicSharedMemorySize, G_SMEM_BYTES);
    cudaFuncSetAttribute(gemm_mma_kernel<0>,
                         cudaFuncAttributeMaxDynamicSharedMemorySize, G_SMEM_BYTES);

    // 1) QKV projection -> half q/k/v
    {
        dim3 grid(3 * C / 128, M / 128);   // (24, 32)
        gemm_mma_kernel<1><<<grid, 256, G_SMEM_BYTES>>>(xh, wqkvh, bqkv,
                                                        q, k, v, M, 3 * C, C);
    }

    // 2) Flash attention (causal) -> yt (half)
    {
        cudaFuncSetAttribute(flash_fa2_kernel,
                             cudaFuncAttributeMaxDynamicSharedMemorySize, F_SMEM);
        dim3 grid(2048 / 128, 32);         // (16, 32)
        flash_fa2_kernel<<<grid, 256, F_SMEM>>>(q, k, v, yt);
    }

    // 3) Output projection -> fp32 out
    {
        dim3 grid(C / 128, M / 128);       // (8, 32)
        gemm_mma_kernel<0><<<grid, 256, G_SMEM_BYTES>>>(yt, wprojh, bproj,
                                                        out, out, out, M, C, C);
    }
}

// round 12
// speedup vs baseline: 1.5840x; 1.0110x over previous
#include <cuda_runtime.h>
#include <cuda_fp16.h>
#include <cstdint>

// ---------------------------------------------------------------------------
// Scratch (device globals)
// ---------------------------------------------------------------------------
__device__ __half g_q [2u * 2048u * 1024u];
__device__ __half g_k [2u * 2048u * 1024u];
__device__ __half g_v [2u * 2048u * 1024u];
__device__ __half g_yt[2u * 2048u * 1024u];
__device__ __half g_xh   [4096u * 1024u];
__device__ __half g_wqkvh[1024u * 3072u];
__device__ __half g_wprojh[1024u * 1024u];

// ---------------------------------------------------------------------------
// cp.async helpers
// ---------------------------------------------------------------------------
__device__ __forceinline__ uint32_t smem_u32(const void* p) {
    return (uint32_t)__cvta_generic_to_shared(p);
}
__device__ __forceinline__ void cp16(uint32_t dst, const void* src) {
    asm volatile("cp.async.cg.shared.global [%0], [%1], 16;"
                 :: "r"(dst), "l"(src) : "memory");
}
__device__ __forceinline__ void cp_commit() {
    asm volatile("cp.async.commit_group;" ::: "memory");
}
template <int N>
__device__ __forceinline__ void cp_wait() {
    asm volatile("cp.async.wait_group %0;" :: "n"(N) : "memory");
}

// ---------------------------------------------------------------------------
// mma / ldmatrix helpers
// ---------------------------------------------------------------------------
__device__ __forceinline__ void mma16816(float* c, const uint32_t* a,
                                         uint32_t b0, uint32_t b1) {
    asm volatile(
        "mma.sync.aligned.m16n8k16.row.col.f32.f16.f16.f32 "
        "{%0,%1,%2,%3}, {%4,%5,%6,%7}, {%8,%9}, {%0,%1,%2,%3};"
        : "+f"(c[0]), "+f"(c[1]), "+f"(c[2]), "+f"(c[3])
        : "r"(a[0]), "r"(a[1]), "r"(a[2]), "r"(a[3]), "r"(b0), "r"(b1));
}
__device__ __forceinline__ void ldsm4(uint32_t& r0, uint32_t& r1,
                                      uint32_t& r2, uint32_t& r3, uint32_t a) {
    asm volatile("ldmatrix.sync.aligned.m8n8.x4.shared.b16 {%0,%1,%2,%3}, [%4];"
                 : "=r"(r0), "=r"(r1), "=r"(r2), "=r"(r3) : "r"(a));
}
__device__ __forceinline__ void ldsm4t(uint32_t& r0, uint32_t& r1,
                                       uint32_t& r2, uint32_t& r3, uint32_t a) {
    asm volatile("ldmatrix.sync.aligned.m8n8.x4.trans.shared.b16 {%0,%1,%2,%3}, [%4];"
                 : "=r"(r0), "=r"(r1), "=r"(r2), "=r"(r3) : "r"(a));
}

// ---------------------------------------------------------------------------
// Combined fp32 -> fp16 conversion (x, Wqkv, Wproj in one launch)
// ---------------------------------------------------------------------------
#define N8_X  (4096u * 1024u / 8u)
#define N8_WQ (1024u * 3072u / 8u)
#define N8_WP (1024u * 1024u / 8u)

__global__ void to_half3_kernel(const float* __restrict__ x,
                                const float* __restrict__ wq,
                                const float* __restrict__ wp,
                                __half* __restrict__ xh,
                                __half* __restrict__ wqh,
                                __half* __restrict__ wph)
{
    uint32_t i = blockIdx.x * blockDim.x + threadIdx.x;
    const float* in;
    __half* out;
    uint32_t j;
    if (i < N8_X)                { in = x;  out = xh;  j = i; }
    else if (i < N8_X + N8_WQ)   { in = wq; out = wqh; j = i - N8_X; }
    else if (i < N8_X + N8_WQ + N8_WP) { in = wp; out = wph; j = i - N8_X - N8_WQ; }
    else return;
    float4 a = ((const float4*)in)[j * 2];
    float4 b = ((const float4*)in)[j * 2 + 1];
    __half h[8];
    h[0] = __float2half_rn(a.x); h[1] = __float2half_rn(a.y);
    h[2] = __float2half_rn(a.z); h[3] = __float2half_rn(a.w);
    h[4] = __float2half_rn(b.x); h[5] = __float2half_rn(b.y);
    h[6] = __float2half_rn(b.z); h[7] = __float2half_rn(b.w);
    ((uint4*)out)[j] = *(uint4*)h;
}

// ---------------------------------------------------------------------------
// FP16 raw-mma GEMM (fp32 accumulate), BK=64, 3-stage cp.async, 2 CTAs/SM.
// C = (A[M,K] @ B[K,N] + bias[N]) * out_scale_for_q
// BM=BN=128, 256 thr (8 warps 4x2), warp tile 32x64. 16 barriers total (K=1024).
// ROUND_OUT=1: store half (and scale Q buffer by 0.125); 0: store fp32.
// ---------------------------------------------------------------------------
#define G_ALD 72              // halves (64 + 8 pad)
#define G_BLD 136             // halves (128 + 8 pad)
#define G_ASZ (128 * G_ALD)   // 9216 halves per A stage
#define G_BSZ (64 * G_BLD)    // 8704 halves per B stage
#define G_STG 3
#define G_SMEM_BYTES (G_STG * (G_ASZ + G_BSZ) * 2)   // 107520

template <int ROUND_OUT>
__global__ __launch_bounds__(256, 2) void gemm_mma_kernel(
    const __half* __restrict__ A, const __half* __restrict__ B,
    const float* __restrict__ bias,
    void* __restrict__ out0v, void* __restrict__ out1v, void* __restrict__ out2v,
    int M, int N, int K)
{
    extern __shared__ char gsmc[];
    __half* gsm = (__half*)gsmc;
    const uint32_t smb = smem_u32(gsmc);

    const int tid  = threadIdx.x;
    const int wid  = tid >> 5;
    const int lane = tid & 31;
    const int wmi  = wid & 3;
    const int wni  = wid >> 2;
    const int m0   = blockIdx.y * 128;
    const int n0   = blockIdx.x * 128;

    const int a_row = (lane & 15);
    const int a_col = (lane >> 4) << 3;
    const int b_row = (lane & 7) + (((lane >> 3) & 1) << 3);
    const int b_col = (lane >> 4) << 3;

    float cfr[2][8][4];
#pragma unroll
    for (int mi = 0; mi < 2; ++mi)
#pragma unroll
        for (int nt = 0; nt < 8; ++nt)
#pragma unroll
            for (int j = 0; j < 4; ++j) cfr[mi][nt][j] = 0.0f;

    const int iters = K >> 6;   // K/64

    auto issue_stage = [&](int stage) {
        const int s = stage % G_STG;
        const int k0 = stage << 6;
        __half* as = gsm + s * G_ASZ;
        __half* bs = gsm + G_STG * G_ASZ + s * G_BSZ;
        // A: 128 rows x 64 halves = 1024 chunks of 8
#pragma unroll
        for (int t = 0; t < 4; ++t) {
            int f = tid + t * 256;
            int r = f >> 3, c8 = (f & 7) << 3;
            cp16(smem_u32(as + r * G_ALD + c8),
                 A + (size_t)(m0 + r) * K + k0 + c8);
        }
        // B: 64 rows x 128 halves = 1024 chunks of 8
#pragma unroll
        for (int t = 0; t < 4; ++t) {
            int f = tid + t * 256;
            int r = f >> 4, c8 = (f & 15) << 3;
            cp16(smem_u32(bs + r * G_BLD + c8),
                 B + (size_t)(k0 + r) * N + n0 + c8);
        }
        cp_commit();
    };

    issue_stage(0);
    issue_stage(1);

    for (int it = 0; it < iters; ++it) {
        cp_wait<1>();
        __syncthreads();

        if (it + 2 < iters) issue_stage(it + 2);
        else                cp_commit();

        const int s = it % G_STG;
        const uint32_t a_base = smb + (s * G_ASZ
                              + (wmi * 32 + a_row) * G_ALD + a_col) * 2;
        const uint32_t b_base = smb + (G_STG * G_ASZ + s * G_BSZ
                              + b_row * G_BLD + wni * 64 + b_col) * 2;

#pragma unroll
        for (int ks = 0; ks < 4; ++ks) {
            uint32_t af[2][4];
#pragma unroll
            for (int mi = 0; mi < 2; ++mi)
                ldsm4(af[mi][0], af[mi][1], af[mi][2], af[mi][3],
                      a_base + (mi * 16 * G_ALD + ks * 16) * 2);
            uint32_t bf[4][4];
#pragma unroll
            for (int p = 0; p < 4; ++p)
                ldsm4t(bf[p][0], bf[p][1], bf[p][2], bf[p][3],
                       b_base + (ks * 16 * G_BLD + p * 16) * 2);
#pragma unroll
            for (int mi = 0; mi < 2; ++mi)
#pragma unroll
                for (int p = 0; p < 4; ++p) {
                    mma16816(cfr[mi][2 * p],     af[mi], bf[p][0], bf[p][1]);
                    mma16816(cfr[mi][2 * p + 1], af[mi], bf[p][2], bf[p][3]);
                }
        }
    }

    // ---- Epilogue: bias (+ 0.125 scale for the Q buffer) + store ----
    const int nc = n0 & 1023;
    const int colw = wni * 64 + 2 * (lane & 3);
    float2 bv[8];
#pragma unroll
    for (int nt = 0; nt < 8; ++nt) {
        bv[nt].x = bias[n0 + colw + nt * 8];
        bv[nt].y = bias[n0 + colw + nt * 8 + 1];
    }
    const int row0 = m0 + wmi * 32 + (lane >> 2);

    if (ROUND_OUT) {
        __half* outp = (n0 < 1024) ? (__half*)out0v
                     : ((n0 < 2048) ? (__half*)out1v : (__half*)out2v);
        const float osc = (n0 < 1024) ? 0.125f : 1.0f;   // Q pre-scaled
#pragma unroll
        for (int mi = 0; mi < 2; ++mi) {
#pragma unroll
            for (int nt = 0; nt < 8; ++nt) {
                int col = nc + colw + nt * 8;
                __half2 v0 = __floats2half2_rn((cfr[mi][nt][0] + bv[nt].x) * osc,
                                               (cfr[mi][nt][1] + bv[nt].y) * osc);
                __half2 v1 = __floats2half2_rn((cfr[mi][nt][2] + bv[nt].x) * osc,
                                               (cfr[mi][nt][3] + bv[nt].y) * osc);
                *(__half2*)(outp + (size_t)(row0 + mi * 16) * 1024 + col) = v0;
                *(__half2*)(outp + (size_t)(row0 + mi * 16 + 8) * 1024 + col) = v1;
            }
        }
    } else {
        float* outp = (n0 < 1024) ? (float*)out0v
                    : ((n0 < 2048) ? (float*)out1v : (float*)out2v);
#pragma unroll
        for (int mi = 0; mi < 2; ++mi) {
#pragma unroll
            for (int nt = 0; nt < 8; ++nt) {
                int col = nc + colw + nt * 8;
                float2 v0 = { cfr[mi][nt][0] + bv[nt].x, cfr[mi][nt][1] + bv[nt].y };
                float2 v1 = { cfr[mi][nt][2] + bv[nt].x, cfr[mi][nt][3] + bv[nt].y };
                *(float2*)(outp + (size_t)(row0 + mi * 16) * 1024 + col) = v0;
                *(float2*)(outp + (size_t)(row0 + mi * 16 + 8) * 1024 + col) = v1;
            }
        }
    }
}

// ---------------------------------------------------------------------------
// Flash attention (causal), FA2-style. Br=128, Bc=64, hd=64, 256 thr.
// Q pre-scaled by GEMM1. Q + 3-deep K/V pipeline all via cp.async.
// ---------------------------------------------------------------------------
#define FLD 72
#define FQ_OFF  0
#define FK_OFF  18432                 // 3 x 9216
#define FV_OFF  (18432 + 27648)
#define F_SMEM  (18432 + 2 * 27648)  // 73728

__global__ __launch_bounds__(256) void flash_fa2_kernel(
    const __half* __restrict__ Qg, const __half* __restrict__ Kg,
    const __half* __restrict__ Vg, __half* __restrict__ yt)
{
    extern __shared__ char smc[];
    const uint32_t smb = smem_u32(smc);
    const uint32_t kbA[3] = { smb + FK_OFF, smb + FK_OFF + 9216, smb + FK_OFF + 18432 };
    const uint32_t vbA[3] = { smb + FV_OFF, smb + FV_OFF + 9216, smb + FV_OFF + 18432 };

    const int qt   = gridDim.x - 1 - blockIdx.x;
    const int bh   = blockIdx.y;
    const int tid  = threadIdx.x;
    const int w    = tid >> 5;
    const int lane = tid & 31;

    const int q_row = (lane & 15);
    const int q_col = (lane >> 4) << 3;
    const int k_row = (lane & 7) + ((lane >> 4) << 3);
    const int k_col = ((lane >> 3) & 1) << 3;
    const int v_row = (lane & 7) + (((lane >> 3) & 1) << 3);
    const int v_col = (lane >> 4) << 3;

    const size_t head_off = (size_t)bh * 131072u;
    const __half* qg = Qg + head_off + (size_t)qt * 8192u;
    const __half* kg = Kg + head_off;
    const __half* vg = Vg + head_off;

    // Q via cp.async (pre-scaled by GEMM1)
#pragma unroll
    for (int t = 0; t < 4; ++t) {
        int f = tid + t * 256;
        int rr = f >> 3, c8 = (f & 7) << 3;
        cp16(smb + FQ_OFF + (rr * FLD + c8) * 2, qg + rr * 64 + c8);
    }
    cp_commit();

    auto issue_kv = [&](int kt) {
        const int buf = kt % 3;
        const __half* kp = kg + (size_t)kt * 4096u;
        const __half* vp = vg + (size_t)kt * 4096u;
#pragma unroll
        for (int t = 0; t < 2; ++t) {
            int f = tid + t * 256;
            int rr = f >> 3, c8 = (f & 7) << 3;
            cp16(kbA[buf] + (rr * FLD + c8) * 2, kp + rr * 64 + c8);
            cp16(vbA[buf] + (rr * FLD + c8) * 2, vp + rr * 64 + c8);
        }
        cp_commit();
    };

    const int n_kt = 2 * (qt + 1);
    issue_kv(0);
    issue_kv(1);

    cp_wait<2>();          // Q resident
    __syncthreads();

    uint32_t qf[4][4];
#pragma unroll
    for (int kk = 0; kk < 4; ++kk) {
        uint32_t a = smb + FQ_OFF
                   + ((w * 16 + q_row) * FLD + kk * 16 + q_col) * 2;
        ldsm4(qf[kk][0], qf[kk][1], qf[kk][2], qf[kk][3], a);
    }

    float oacc[8][4];
#pragma unroll
    for (int nt = 0; nt < 8; ++nt)
#pragma unroll
        for (int j = 0; j < 4; ++j) oacc[nt][j] = 0.0f;
    float m_lo = -1e30f, m_hi = -1e30f;
    float l_lo = 0.0f,   l_hi = 0.0f;

    const int row_g_lo = qt * 128 + w * 16 + (lane >> 2);
    const int row_g_hi = row_g_lo + 8;

    for (int kt = 0; kt < n_kt; ++kt) {
        const int buf = kt % 3;
        cp_wait<1>();
        __syncthreads();
        if (kt + 2 < n_kt) issue_kv(kt + 2);
        else               cp_commit();

        float sacc[8][4];
#pragma unroll
        for (int nt = 0; nt < 8; ++nt)
#pragma unroll
            for (int j = 0; j < 4; ++j) sacc[nt][j] = 0.0f;
#pragma unroll
        for (int p = 0; p < 4; ++p) {
#pragma unroll
            for (int kk = 0; kk < 4; ++kk) {
                uint32_t b0, b1, b2, b3;
                uint32_t a = kbA[buf]
                           + ((p * 16 + k_row) * FLD + kk * 16 + k_col) * 2;
                ldsm4(b0, b1, b2, b3, a);
                mma16816(sacc[2 * p],     qf[kk], b0, b1);
                mma16816(sacc[2 * p + 1], qf[kk], b2, b3);
            }
        }

        if (kt >= 2 * qt) {
            const int cb = kt * 64 + 2 * (lane & 3);
#pragma unroll
            for (int nt = 0; nt < 8; ++nt) {
                int c = cb + nt * 8;
                if (c     > row_g_lo) sacc[nt][0] = -1e30f;
                if (c + 1 > row_g_lo) sacc[nt][1] = -1e30f;
                if (c     > row_g_hi) sacc[nt][2] = -1e30f;
                if (c + 1 > row_g_hi) sacc[nt][3] = -1e30f;
            }
        }

        float mx_lo = -1e30f, mx_hi = -1e30f;
#pragma unroll
        for (int nt = 0; nt < 8; ++nt) {
            mx_lo = fmaxf(mx_lo, fmaxf(sacc[nt][0], sacc[nt][1]));
            mx_hi = fmaxf(mx_hi, fmaxf(sacc[nt][2], sacc[nt][3]));
        }
        mx_lo = fmaxf(mx_lo, __shfl_xor_sync(0xffffffffu, mx_lo, 1));
        mx_lo = fmaxf(mx_lo, __shfl_xor_sync(0xffffffffu, mx_lo, 2));
        mx_hi = fmaxf(mx_hi, __shfl_xor_sync(0xffffffffu, mx_hi, 1));
        mx_hi = fmaxf(mx_hi, __shfl_xor_sync(0xffffffffu, mx_hi, 2));

        const float mn_lo = fmaxf(m_lo, mx_lo);
        const float mn_hi = fmaxf(m_hi, mx_hi);
        const float al_lo = __expf(m_lo - mn_lo);
        const float al_hi = __expf(m_hi - mn_hi);
        m_lo = mn_lo; m_hi = mn_hi;

        float sum_lo = 0.0f, sum_hi = 0.0f;
        uint32_t pfr[4][4];
#pragma unroll
        for (int nt = 0; nt < 8; ++nt) {
            float p0 = __expf(sacc[nt][0] - mn_lo);
            float p1 = __expf(sacc[nt][1] - mn_lo);
            float p2 = __expf(sacc[nt][2] - mn_hi);
            float p3 = __expf(sacc[nt][3] - mn_hi);
            sum_lo += p0 + p1;
            sum_hi += p2 + p3;
            __half2 h01 = __floats2half2_rn(p0, p1);
            __half2 h23 = __floats2half2_rn(p2, p3);
            pfr[nt >> 1][(nt & 1) * 2 + 0] = *(uint32_t*)&h01;
            pfr[nt >> 1][(nt & 1) * 2 + 1] = *(uint32_t*)&h23;
        }
        l_lo = l_lo * al_lo + sum_lo;
        l_hi = l_hi * al_hi + sum_hi;

#pragma unroll
        for (int nt = 0; nt < 8; ++nt) {
            oacc[nt][0] *= al_lo; oacc[nt][1] *= al_lo;
            oacc[nt][2] *= al_hi; oacc[nt][3] *= al_hi;
        }

#pragma unroll
        for (int p = 0; p < 4; ++p) {
#pragma unroll
            for (int t = 0; t < 4; ++t) {
                uint32_t b0, b1, b2, b3;
                uint32_t a = vbA[buf]
                           + ((t * 16 + v_row) * FLD + p * 16 + v_col) * 2;
                ldsm4t(b0, b1, b2, b3, a);
                mma16816(oacc[2 * p],     pfr[t], b0, b1);
                mma16816(oacc[2 * p + 1], pfr[t], b2, b3);
            }
        }
    }

    l_lo += __shfl_xor_sync(0xffffffffu, l_lo, 1);
    l_lo += __shfl_xor_sync(0xffffffffu, l_lo, 2);
    l_hi += __shfl_xor_sync(0xffffffffu, l_hi, 1);
    l_hi += __shfl_xor_sync(0xffffffffu, l_hi, 2);
    const float inv_lo = 1.0f / l_lo;
    const float inv_hi = 1.0f / l_hi;

    const int b = bh >> 4;
    const int h = bh & 15;
    const int tq_lo = qt * 128 + w * 16 + (lane >> 2);
    __half* dst_lo = yt + ((size_t)(b * 2048 + tq_lo)) * 1024u + h * 64 + 2 * (lane & 3);
    __half* dst_hi = dst_lo + 8u * 1024u;
#pragma unroll
    for (int nt = 0; nt < 8; ++nt) {
        __half2 vlo = __floats2half2_rn(oacc[nt][0] * inv_lo, oacc[nt][1] * inv_lo);
        __half2 vhi = __floats2half2_rn(oacc[nt][2] * inv_hi, oacc[nt][3] * inv_hi);
        *(__half2*)(dst_lo + nt * 8) = vlo;
        *(__half2*)(dst_hi + nt * 8) = vhi;
    }
}

// ---------------------------------------------------------------------------
// Launch
// ---------------------------------------------------------------------------
extern "C" void kernel_launch(void* const* d_in, const int* in_sizes, int n_in,
                              void* d_out, int out_size)
{
    const float* x     = (const float*)d_in[0];
    const float* Wqkv  = (const float*)d_in[1];
    const float* bqkv  = (const float*)d_in[2];
    const float* Wproj = (const float*)d_in[3];
    const float* bproj = (const float*)d_in[4];
    float* out = (float*)d_out;

    __half *q, *k, *v, *yt, *xh, *wqkvh, *wprojh;
    cudaGetSymbolAddress((void**)&q,  g_q);
    cudaGetSymbolAddress((void**)&k,  g_k);
    cudaGetSymbolAddress((void**)&v,  g_v);
    cudaGetSymbolAddress((void**)&yt, g_yt);
    cudaGetSymbolAddress((void**)&xh, g_xh);
    cudaGetSymbolAddress((void**)&wqkvh, g_wqkvh);
    cudaGetSymbolAddress((void**)&wprojh, g_wprojh);

    const int M = 4096, C = 1024;

    // 0) fp32 -> fp16 conversion (single launch)
    {
        uint32_t total = N8_X + N8_WQ + N8_WP;
        to_half3_kernel<<<(total + 255) / 256, 256>>>(x, Wqkv, Wproj,
                                                      xh, wqkvh, wprojh);
    }

    cudaFuncSetAttribute(gemm_mma_kernel<1>,
                         cudaFuncAttributeMaxDynamicSharedMemorySize, G_SMEM_BYTES);
    cudaFuncSetAttribute(gemm_mma_kernel<0>,
                         cudaFuncAttributeMaxDynamicSharedMemorySize, G_SMEM_BYTES);

    // 1) QKV projection -> half q/k/v (Q pre-scaled by 0.125)
    {
        dim3 grid(3 * C / 128, M / 128);   // (24, 32)
        gemm_mma_kernel<1><<<grid, 256, G_SMEM_BYTES>>>(xh, wqkvh, bqkv,
                                                        q, k, v, M, 3 * C, C);
    }

    // 2) Flash attention (causal) -> yt (half)
    {
        cudaFuncSetAttribute(flash_fa2_kernel,
                             cudaFuncAttributeMaxDynamicSharedMemorySize, F_SMEM);
        dim3 grid(2048 / 128, 32);         // (16, 32)
        flash_fa2_kernel<<<grid, 256, F_SMEM>>>(q, k, v, yt);
    }

    // 3) Output projection -> fp32 out
    {
        dim3 grid(C / 128, M / 128);       // (8, 32)
        gemm_mma_kernel<0><<<grid, 256, G_SMEM_BYTES>>>(yt, wprojh, bproj,
                                                        out, out, out, M, C, C);
    }
}